// round 2
// baseline (speedup 1.0000x reference)
#include <cuda_runtime.h>
#include <cuda_bf16.h>
#include <math.h>

// ---------------------------------------------------------------------------
// Problem constants
// ---------------------------------------------------------------------------
#define SQ   128            // seq len
#define BB   128            // batch
#define EE   256            // embed dim
#define HH   256            // hidden
#define G4   1024           // 4*H
#define D2   512            // 2*H
#define MBS  (BB*SQ)        // 16384
#define MX   (3*MBS)        // 49152 rows of X
#define OUTREG (BB*SQ*D2)   // 8388608 floats per output tensor

// ---------------------------------------------------------------------------
// Device scratch (static __device__ arrays -- the sanctioned workaround)
// ---------------------------------------------------------------------------
__device__ float g_X    [3*MBS*EE];     //  50 MB  embedded inputs [seq][b][s][E]
__device__ float g_XpreF[3*MBS*G4];     // 201 MB  X@Wih_f^T + bias_f
__device__ float g_XpreB[3*MBS*G4];     // 201 MB
__device__ float g_WhhTf[HH*G4];        //   1 MB  Whh_f transposed [k][g]
__device__ float g_WhhTb[HH*G4];
__device__ float g_biasf[G4];
__device__ float g_biasb[G4];
__device__ float g_Y    [3*MBS*D2];     // 100 MB  BiLSTM outputs [seq][b][s][2H]
__device__ float g_Ct   [2*MBS*D2];     //  67 MB  tanh(S1(C)) for C and C2
__device__ float g_Hm   [BB*SQ*SQ];     // 8.4 MB
__device__ float g_AQ   [BB*SQ*SQ];
__device__ float g_AC   [BB*SQ*SQ];

// ---------------------------------------------------------------------------
// Prep: bias = bih + bhh ; WhhT[k][g] = Whh[g][k]
// ---------------------------------------------------------------------------
__global__ void prep_kernel(const float* __restrict__ WhhF, const float* __restrict__ WhhB,
                            const float* __restrict__ bihF, const float* __restrict__ bhhF,
                            const float* __restrict__ bihB, const float* __restrict__ bhhB,
                            float* __restrict__ whhTf, float* __restrict__ whhTb,
                            float* __restrict__ biasf, float* __restrict__ biasb)
{
    int gid = blockIdx.x * 256 + threadIdx.x;      // 262144 total
    int g = gid & (G4 - 1);
    int k = gid >> 10;
    whhTf[k * G4 + g] = WhhF[g * HH + k];
    whhTb[k * G4 + g] = WhhB[g * HH + k];
    if (gid < G4) {
        biasf[gid] = bihF[gid] + bhhF[gid];
        biasb[gid] = bihB[gid] + bhhB[gid];
    }
}

// ---------------------------------------------------------------------------
// Embedding gather: X[seq][b][s][:] = emb[tok[seq][s][b]][:]
// ---------------------------------------------------------------------------
__global__ void embed_kernel(const int* __restrict__ tq, const int* __restrict__ tc,
                             const int* __restrict__ tc2,
                             const float4* __restrict__ emb, float4* __restrict__ X)
{
    int gid = blockIdx.x * 256 + threadIdx.x;      // 3*16384*64 = 3145728 total
    int c4  = gid & 63;
    int row = gid >> 6;                            // 0..49151
    int seq = row / MBS;
    int rb  = row - seq * MBS;
    int b   = rb >> 7, s = rb & 127;
    const int* tok = (seq == 0) ? tq : ((seq == 1) ? tc : tc2);
    int t = tok[s * BB + b];
    X[(size_t)row * 64 + c4] = emb[(size_t)t * 64 + c4];
}

// ---------------------------------------------------------------------------
// Generic tiled SGEMM:  C = A[M,K] * op(B) (+bias) (+tanh)
//   BT=true : B stored [N,K] row-major (use B^T)
//   BT=false: B stored [K,N] row-major
//   EPI: 0=none, 1=+bias[n], 2=tanh(x+bias[n])
// Requires M%128==0, N%128==0, K%8==0 (true for all our shapes).
// ---------------------------------------------------------------------------
template<bool BT, int EPI>
__global__ __launch_bounds__(256) void sgemm_kernel(
    int M, int N, int K,
    const float* __restrict__ A, int lda, size_t strideA,
    const float* __restrict__ B, int ldb, size_t strideB,
    float* __restrict__ C, int ldc, size_t strideC,
    const float* __restrict__ bias)
{
    __shared__ float As[8][128];
    __shared__ float Bs[8][128];
    int bx = blockIdx.x, by = blockIdx.y, bz = blockIdx.z;
    const float* Ap = A + (size_t)bz * strideA + (size_t)by * 128 * lda;
    const float* Bp = B + (size_t)bz * strideB;
    float* Cp = C + (size_t)bz * strideC + (size_t)by * 128 * ldc + (size_t)bx * 128;

    int tid = threadIdx.x;
    int tx = tid & 15, ty = tid >> 4;
    int lRow = tid >> 1, lK4 = (tid & 1) * 4;      // for [rows][8] style tiles
    int bK = tid >> 5, bN4 = (tid & 31) * 4;       // for [8][128] NN tile

    float acc[8][8];
#pragma unroll
    for (int i = 0; i < 8; i++)
#pragma unroll
        for (int j = 0; j < 8; j++) acc[i][j] = 0.f;

    for (int k0 = 0; k0 < K; k0 += 8) {
        float4 av = *reinterpret_cast<const float4*>(Ap + (size_t)lRow * lda + k0 + lK4);
        As[lK4 + 0][lRow] = av.x; As[lK4 + 1][lRow] = av.y;
        As[lK4 + 2][lRow] = av.z; As[lK4 + 3][lRow] = av.w;
        if constexpr (BT) {
            float4 bv = *reinterpret_cast<const float4*>(
                Bp + ((size_t)bx * 128 + lRow) * ldb + k0 + lK4);
            Bs[lK4 + 0][lRow] = bv.x; Bs[lK4 + 1][lRow] = bv.y;
            Bs[lK4 + 2][lRow] = bv.z; Bs[lK4 + 3][lRow] = bv.w;
        } else {
            float4 bv = *reinterpret_cast<const float4*>(
                Bp + (size_t)(k0 + bK) * ldb + bx * 128 + bN4);
            *reinterpret_cast<float4*>(&Bs[bK][bN4]) = bv;
        }
        __syncthreads();
#pragma unroll
        for (int kk = 0; kk < 8; kk++) {
            float ar[8], br[8];
            *reinterpret_cast<float4*>(&ar[0]) = *reinterpret_cast<const float4*>(&As[kk][ty * 8]);
            *reinterpret_cast<float4*>(&ar[4]) = *reinterpret_cast<const float4*>(&As[kk][ty * 8 + 4]);
            *reinterpret_cast<float4*>(&br[0]) = *reinterpret_cast<const float4*>(&Bs[kk][tx * 8]);
            *reinterpret_cast<float4*>(&br[4]) = *reinterpret_cast<const float4*>(&Bs[kk][tx * 8 + 4]);
#pragma unroll
            for (int i = 0; i < 8; i++)
#pragma unroll
                for (int j = 0; j < 8; j++)
                    acc[i][j] += ar[i] * br[j];
        }
        __syncthreads();
    }

    int gcol = bx * 128 + tx * 8;
#pragma unroll
    for (int i = 0; i < 8; i++) {
        int row = ty * 8 + i;
#pragma unroll
        for (int jj = 0; jj < 8; jj += 4) {
            float4 v;
            v.x = acc[i][jj + 0]; v.y = acc[i][jj + 1];
            v.z = acc[i][jj + 2]; v.w = acc[i][jj + 3];
            if constexpr (EPI >= 1) {
                v.x += bias[gcol + jj + 0]; v.y += bias[gcol + jj + 1];
                v.z += bias[gcol + jj + 2]; v.w += bias[gcol + jj + 3];
            }
            if constexpr (EPI == 2) {
                v.x = tanhf(v.x); v.y = tanhf(v.y);
                v.z = tanhf(v.z); v.w = tanhf(v.w);
            }
            *reinterpret_cast<float4*>(Cp + (size_t)row * ldc + tx * 8 + jj) = v;
        }
    }
}

// ---------------------------------------------------------------------------
// LSTM recurrence: 768 independent rows (3 seq x 2 dir x 128 batch).
// Each CTA owns LR rows of ONE (seq,dir) stream -> zero inter-CTA sync.
// h lives in smem (needed by all 256 threads), c in registers.
// Thread j owns hidden unit j: computes gates {j, 256+j, 512+j, 768+j}.
// ---------------------------------------------------------------------------
#define LR  6
#define CPS 22   // CTAs per stream: 22*6 = 132 >= 128

__global__ __launch_bounds__(256) void lstm_kernel(
    const float* __restrict__ xpreF, const float* __restrict__ xpreB,
    const float* __restrict__ whhTf, const float* __restrict__ whhTb,
    const float* __restrict__ h_q, const float* __restrict__ c_q,
    const float* __restrict__ h_c, const float* __restrict__ c_c,
    const float* __restrict__ h_c2, const float* __restrict__ c_c2,
    float* __restrict__ Y)
{
    int cta = blockIdx.x;
    int sd = cta / CPS, loc = cta % CPS;
    int seq = sd >> 1, dir = sd & 1;
    int b0 = loc * LR;
    int nr = 128 - b0; if (nr > LR) nr = LR; if (nr <= 0) return;

    const float* xpre = (dir ? xpreB : xpreF) + (size_t)seq * MBS * G4;
    const float* whhT = dir ? whhTb : whhTf;
    const float* hptr = (seq == 0) ? h_q : ((seq == 1) ? h_c : h_c2);
    const float* cptr = (seq == 0) ? c_q : ((seq == 1) ? c_c : c_c2);

    __shared__ float hs[LR][HH];
    int j = threadIdx.x;
    float creg[LR];
#pragma unroll
    for (int r = 0; r < LR; r++) {
        if (r < nr) {
            size_t off = ((size_t)dir * BB + b0 + r) * HH + j;
            hs[r][j] = hptr[off];
            creg[r]  = cptr[off];
        } else { hs[r][j] = 0.f; creg[r] = 0.f; }
    }
    __syncthreads();

    for (int t = 0; t < SQ; t++) {
        int te = dir ? (SQ - 1 - t) : t;
        float a0[LR], a1[LR], a2[LR], a3[LR];
#pragma unroll
        for (int r = 0; r < LR; r++) { a0[r] = 0.f; a1[r] = 0.f; a2[r] = 0.f; a3[r] = 0.f; }

        const float* wp = whhT + j;
#pragma unroll 4
        for (int k = 0; k < HH; k++) {
            float w0 = wp[0], w1 = wp[256], w2 = wp[512], w3 = wp[768];
            wp += G4;
#pragma unroll
            for (int r = 0; r < LR; r++) {
                float hk = hs[r][k];
                a0[r] += w0 * hk; a1[r] += w1 * hk;
                a2[r] += w2 * hk; a3[r] += w3 * hk;
            }
        }
        __syncthreads();   // all reads of old h complete
#pragma unroll
        for (int r = 0; r < LR; r++) {
            if (r < nr) {
                const float* xp = xpre + (((size_t)(b0 + r) * SQ + te) * G4);
                float gi = a0[r] + xp[j];
                float gf = a1[r] + xp[256 + j];
                float gg = a2[r] + xp[512 + j];
                float go = a3[r] + xp[768 + j];
                float i_ = 1.f / (1.f + __expf(-gi));
                float f_ = 1.f / (1.f + __expf(-gf));
                float g_ = tanhf(gg);
                float o_ = 1.f / (1.f + __expf(-go));
                float c = f_ * creg[r] + i_ * g_;
                creg[r] = c;
                float h = o_ * tanhf(c);
                hs[r][j] = h;
                Y[(((size_t)(seq * BB + b0 + r)) * SQ + te) * D2 + dir * HH + j] = h;
            }
        }
        __syncthreads();   // new h visible before next step
    }
}

// ---------------------------------------------------------------------------
// Softmax over rows of Hm (flat [16384][128]) -> AQ (same layout)
// ---------------------------------------------------------------------------
__global__ void row_softmax(const float* __restrict__ Hm, float* __restrict__ AQ)
{
    int warp = (blockIdx.x * blockDim.x + threadIdx.x) >> 5;   // 0..16383
    int lane = threadIdx.x & 31;
    const float* base = Hm + (size_t)warp * SQ;
    float v[4], m = -1e30f;
#pragma unroll
    for (int u = 0; u < 4; u++) { v[u] = base[lane + 32 * u]; m = fmaxf(m, v[u]); }
#pragma unroll
    for (int o = 16; o > 0; o >>= 1) m = fmaxf(m, __shfl_xor_sync(0xffffffffu, m, o));
    float s = 0.f;
#pragma unroll
    for (int u = 0; u < 4; u++) { v[u] = __expf(v[u] - m); s += v[u]; }
#pragma unroll
    for (int o = 16; o > 0; o >>= 1) s += __shfl_xor_sync(0xffffffffu, s, o);
    float inv = 1.f / s;
    float* out = AQ + (size_t)warp * SQ;
#pragma unroll
    for (int u = 0; u < 4; u++) out[lane + 32 * u] = v[u] * inv;
}

// ---------------------------------------------------------------------------
// Column softmax: AC[b][s][t] = exp(Hm[b][t][s]-m_s)/sum_t' exp(Hm[b][t'][s]-m_s)
// ---------------------------------------------------------------------------
__global__ void col_softmax(const float* __restrict__ Hm, float* __restrict__ AC)
{
    int warp = (blockIdx.x * blockDim.x + threadIdx.x) >> 5;   // 0..16383
    int lane = threadIdx.x & 31;
    int b = warp >> 7, s = warp & 127;
    const float* base = Hm + (size_t)b * SQ * SQ + s;          // column s of batch b
    float v[4], m = -1e30f;
#pragma unroll
    for (int u = 0; u < 4; u++) { v[u] = base[(size_t)(lane + 32 * u) * SQ]; m = fmaxf(m, v[u]); }
#pragma unroll
    for (int o = 16; o > 0; o >>= 1) m = fmaxf(m, __shfl_xor_sync(0xffffffffu, m, o));
    float sm = 0.f;
#pragma unroll
    for (int u = 0; u < 4; u++) { v[u] = __expf(v[u] - m); sm += v[u]; }
#pragma unroll
    for (int o = 16; o > 0; o >>= 1) sm += __shfl_xor_sync(0xffffffffu, sm, o);
    float inv = 1.f / sm;
    float* out = AC + (size_t)b * SQ * SQ + (size_t)s * SQ;
#pragma unroll
    for (int u = 0; u < 4; u++) out[lane + 32 * u] = v[u] * inv;
}

// ---------------------------------------------------------------------------
// Host-side GEMM dispatch
// ---------------------------------------------------------------------------
static void run_gemm(bool bt, int epi, int M, int N, int K,
                     const float* A, int lda, size_t sA,
                     const float* B, int ldb, size_t sB,
                     float* C, int ldc, size_t sC,
                     const float* bias, int batch)
{
    dim3 grid(N / 128, M / 128, batch), block(256);
    if (bt) {
        if (epi == 0)      sgemm_kernel<true, 0><<<grid, block>>>(M, N, K, A, lda, sA, B, ldb, sB, C, ldc, sC, bias);
        else if (epi == 1) sgemm_kernel<true, 1><<<grid, block>>>(M, N, K, A, lda, sA, B, ldb, sB, C, ldc, sC, bias);
        else               sgemm_kernel<true, 2><<<grid, block>>>(M, N, K, A, lda, sA, B, ldb, sB, C, ldc, sC, bias);
    } else {
        sgemm_kernel<false, 0><<<grid, block>>>(M, N, K, A, lda, sA, B, ldb, sB, C, ldc, sC, bias);
    }
}

// ---------------------------------------------------------------------------
// kernel_launch
// ---------------------------------------------------------------------------
extern "C" void kernel_launch(void* const* d_in, const int* in_sizes, int n_in,
                              void* d_out, int out_size)
{
    (void)in_sizes; (void)n_in; (void)out_size;
    const int*   inQ   = (const int*)d_in[1];
    const int*   inC   = (const int*)d_in[2];
    const int*   inC2  = (const int*)d_in[3];
    const float* hidQ  = (const float*)d_in[4];
    const float* celQ  = (const float*)d_in[5];
    const float* hidC  = (const float*)d_in[6];
    const float* celC  = (const float*)d_in[7];
    const float* hidC2 = (const float*)d_in[8];
    const float* celC2 = (const float*)d_in[9];
    const float* emb   = (const float*)d_in[10];
    const float* WihF  = (const float*)d_in[11];
    const float* WhhF  = (const float*)d_in[12];
    const float* bihF  = (const float*)d_in[13];
    const float* bhhF  = (const float*)d_in[14];
    const float* WihB  = (const float*)d_in[15];
    const float* WhhB  = (const float*)d_in[16];
    const float* bihB  = (const float*)d_in[17];
    const float* bhhB  = (const float*)d_in[18];
    const float* S1W   = (const float*)d_in[19];
    const float* S1b   = (const float*)d_in[20];
    float* out = (float*)d_out;

    void *pX, *pXpF, *pXpB, *pWTf, *pWTb, *pBf, *pBb, *pY, *pCt, *pHm, *pAQ, *pAC;
    cudaGetSymbolAddress(&pX,   g_X);
    cudaGetSymbolAddress(&pXpF, g_XpreF);
    cudaGetSymbolAddress(&pXpB, g_XpreB);
    cudaGetSymbolAddress(&pWTf, g_WhhTf);
    cudaGetSymbolAddress(&pWTb, g_WhhTb);
    cudaGetSymbolAddress(&pBf,  g_biasf);
    cudaGetSymbolAddress(&pBb,  g_biasb);
    cudaGetSymbolAddress(&pY,   g_Y);
    cudaGetSymbolAddress(&pCt,  g_Ct);
    cudaGetSymbolAddress(&pHm,  g_Hm);
    cudaGetSymbolAddress(&pAQ,  g_AQ);
    cudaGetSymbolAddress(&pAC,  g_AC);
    float* X    = (float*)pX;
    float* XpF  = (float*)pXpF;
    float* XpB  = (float*)pXpB;
    float* WTf  = (float*)pWTf;
    float* WTb  = (float*)pWTb;
    float* Bf   = (float*)pBf;
    float* Bb   = (float*)pBb;
    float* Y    = (float*)pY;
    float* Ct   = (float*)pCt;
    float* Hm   = (float*)pHm;
    float* AQ   = (float*)pAQ;
    float* AC   = (float*)pAC;

    // 1. prep (bias fold + Whh transpose)
    prep_kernel<<<1024, 256>>>(WhhF, WhhB, bihF, bhhF, bihB, bhhB, WTf, WTb, Bf, Bb);

    // 2. embedding gather for all 3 sequences
    embed_kernel<<<12288, 256>>>(inQ, inC, inC2, (const float4*)emb, (float4*)X);

    // 3. input GEMMs (all timesteps at once): Xpre = X @ Wih^T + (bih+bhh)
    run_gemm(true, 1, MX, G4, EE, X, EE, 0, WihF, EE, 0, XpF, G4, 0, Bf, 1);
    run_gemm(true, 1, MX, G4, EE, X, EE, 0, WihB, EE, 0, XpB, G4, 0, Bb, 1);

    // 4. recurrence: 6 independent (seq,dir) streams, 768 independent rows
    lstm_kernel<<<6 * CPS, 256>>>(XpF, XpB, WTf, WTb,
                                  hidQ, celQ, hidC, celC, hidC2, celC2, Y);

    // 5. tanh projections of C and C2 contexts: Ct = tanh(Y_c @ S1_W^T + S1_b)
    run_gemm(true, 2, MBS, D2, D2, Y + (size_t)1 * MBS * D2, D2, 0,
             S1W, D2, 0, Ct, D2, 0, S1b, 1);
    run_gemm(true, 2, MBS, D2, D2, Y + (size_t)2 * MBS * D2, D2, 0,
             S1W, D2, 0, Ct + (size_t)MBS * D2, D2, 0, S1b, 1);

    // 6. attention for pairs (Q,C) and (Q,C2)
    for (int p = 0; p < 2; p++) {
        // Hm[b] = Q[b] @ Ct[b]^T     [128,512] x [128,512]^T -> [128,128]
        run_gemm(true, 0, SQ, SQ, D2,
                 Y, D2, (size_t)SQ * D2,
                 Ct + (size_t)p * MBS * D2, D2, (size_t)SQ * D2,
                 Hm, SQ, (size_t)SQ * SQ, nullptr, BB);
        row_softmax<<<2048, 256>>>(Hm, AQ);
        col_softmax<<<2048, 256>>>(Hm, AC);
        float* outMQ = out + (size_t)(2 * p) * OUTREG;
        float* outMC = out + (size_t)(2 * p + 1) * OUTREG;
        // MQ[b] = AQ[b] @ Q[b]       [128,128] x [128,512] -> [128,512]
        run_gemm(false, 0, SQ, D2, SQ,
                 AQ, SQ, (size_t)SQ * SQ,
                 Y, D2, (size_t)SQ * D2,
                 outMQ, D2, (size_t)SQ * D2, nullptr, BB);
        // MC[b] = AC[b] @ MQ[b]
        run_gemm(false, 0, SQ, D2, SQ,
                 AC, SQ, (size_t)SQ * SQ,
                 outMQ, D2, (size_t)SQ * D2,
                 outMC, D2, (size_t)SQ * D2, nullptr, BB);
    }
}

// round 3
// speedup vs baseline: 2.0047x; 2.0047x over previous
#include <cuda_runtime.h>
#include <cuda_bf16.h>
#include <math.h>

// ---------------------------------------------------------------------------
// Problem constants
// ---------------------------------------------------------------------------
#define SQ   128            // seq len
#define BB   128            // batch
#define EE   256            // embed dim
#define HH   256            // hidden
#define G4   1024           // 4*H
#define D2   512            // 2*H
#define MBS  (BB*SQ)        // 16384
#define MX   (3*MBS)        // 49152 rows of X
#define OUTREG (BB*SQ*D2)   // 8388608 floats per output tensor

// LSTM-mma geometry
#define WPAD 260
#define HPAD 260
#define GPAD 132
#define LSTM_SMEM_BYTES ((128*WPAD + 64*HPAD) * 4)   // 199,680 B

// ---------------------------------------------------------------------------
// Device scratch
// ---------------------------------------------------------------------------
__device__ float g_X    [3*MBS*EE];     //  50 MB  embedded inputs [seq][b][s][E]
__device__ float g_XpreF[3*MBS*G4];     // 201 MB  X@Wih_f^T + bias_f
__device__ float g_XpreB[3*MBS*G4];     // 201 MB
__device__ float g_biasf[G4];
__device__ float g_biasb[G4];
__device__ float g_Y    [3*MBS*D2];     // 100 MB  BiLSTM outputs [seq][b][s][2H]
__device__ float g_Ct   [2*MBS*D2];     //  67 MB  tanh(S1(C)) for C and C2
__device__ float g_Hm   [BB*SQ*SQ];     // 8.4 MB
__device__ float g_AQ   [BB*SQ*SQ];
__device__ float g_AC   [BB*SQ*SQ];
__device__ int   g_bar  [12];           // barrier counters (6 streams x 2 batch-halves)

// ---------------------------------------------------------------------------
// Prep: bias = bih + bhh ; reset barrier counters (graph replays re-run this)
// ---------------------------------------------------------------------------
__global__ void prep_kernel(const float* __restrict__ bihF, const float* __restrict__ bhhF,
                            const float* __restrict__ bihB, const float* __restrict__ bhhB,
                            float* __restrict__ biasf, float* __restrict__ biasb,
                            int* __restrict__ bars)
{
    int gid = blockIdx.x * 256 + threadIdx.x;
    if (gid < G4) {
        biasf[gid] = bihF[gid] + bhhF[gid];
        biasb[gid] = bihB[gid] + bhhB[gid];
    }
    if (gid < 12) bars[gid] = 0;
}

// ---------------------------------------------------------------------------
// Embedding gather: X[seq][b][s][:] = emb[tok[seq][s][b]][:]
// ---------------------------------------------------------------------------
__global__ void embed_kernel(const int* __restrict__ tq, const int* __restrict__ tc,
                             const int* __restrict__ tc2,
                             const float4* __restrict__ emb, float4* __restrict__ X)
{
    int gid = blockIdx.x * 256 + threadIdx.x;      // 3*16384*64 = 3145728 total
    int c4  = gid & 63;
    int row = gid >> 6;                            // 0..49151
    int seq = row / MBS;
    int rb  = row - seq * MBS;
    int b   = rb >> 7, s = rb & 127;
    const int* tok = (seq == 0) ? tq : ((seq == 1) ? tc : tc2);
    int t = tok[s * BB + b];
    X[(size_t)row * 64 + c4] = emb[(size_t)t * 64 + c4];
}

// ---------------------------------------------------------------------------
// Generic tiled SGEMM (unchanged from passing R2 kernel)
// ---------------------------------------------------------------------------
template<bool BT, int EPI>
__global__ __launch_bounds__(256) void sgemm_kernel(
    int M, int N, int K,
    const float* __restrict__ A, int lda, size_t strideA,
    const float* __restrict__ B, int ldb, size_t strideB,
    float* __restrict__ C, int ldc, size_t strideC,
    const float* __restrict__ bias)
{
    __shared__ float As[8][128];
    __shared__ float Bs[8][128];
    int bx = blockIdx.x, by = blockIdx.y, bz = blockIdx.z;
    const float* Ap = A + (size_t)bz * strideA + (size_t)by * 128 * lda;
    const float* Bp = B + (size_t)bz * strideB;
    float* Cp = C + (size_t)bz * strideC + (size_t)by * 128 * ldc + (size_t)bx * 128;

    int tid = threadIdx.x;
    int tx = tid & 15, ty = tid >> 4;
    int lRow = tid >> 1, lK4 = (tid & 1) * 4;
    int bK = tid >> 5, bN4 = (tid & 31) * 4;

    float acc[8][8];
#pragma unroll
    for (int i = 0; i < 8; i++)
#pragma unroll
        for (int j = 0; j < 8; j++) acc[i][j] = 0.f;

    for (int k0 = 0; k0 < K; k0 += 8) {
        float4 av = *reinterpret_cast<const float4*>(Ap + (size_t)lRow * lda + k0 + lK4);
        As[lK4 + 0][lRow] = av.x; As[lK4 + 1][lRow] = av.y;
        As[lK4 + 2][lRow] = av.z; As[lK4 + 3][lRow] = av.w;
        if constexpr (BT) {
            float4 bv = *reinterpret_cast<const float4*>(
                Bp + ((size_t)bx * 128 + lRow) * ldb + k0 + lK4);
            Bs[lK4 + 0][lRow] = bv.x; Bs[lK4 + 1][lRow] = bv.y;
            Bs[lK4 + 2][lRow] = bv.z; Bs[lK4 + 3][lRow] = bv.w;
        } else {
            float4 bv = *reinterpret_cast<const float4*>(
                Bp + (size_t)(k0 + bK) * ldb + bx * 128 + bN4);
            *reinterpret_cast<float4*>(&Bs[bK][bN4]) = bv;
        }
        __syncthreads();
#pragma unroll
        for (int kk = 0; kk < 8; kk++) {
            float ar[8], br[8];
            *reinterpret_cast<float4*>(&ar[0]) = *reinterpret_cast<const float4*>(&As[kk][ty * 8]);
            *reinterpret_cast<float4*>(&ar[4]) = *reinterpret_cast<const float4*>(&As[kk][ty * 8 + 4]);
            *reinterpret_cast<float4*>(&br[0]) = *reinterpret_cast<const float4*>(&Bs[kk][tx * 8]);
            *reinterpret_cast<float4*>(&br[4]) = *reinterpret_cast<const float4*>(&Bs[kk][tx * 8 + 4]);
#pragma unroll
            for (int i = 0; i < 8; i++)
#pragma unroll
                for (int j = 0; j < 8; j++)
                    acc[i][j] += ar[i] * br[j];
        }
        __syncthreads();
    }

    int gcol = bx * 128 + tx * 8;
#pragma unroll
    for (int i = 0; i < 8; i++) {
        int row = ty * 8 + i;
#pragma unroll
        for (int jj = 0; jj < 8; jj += 4) {
            float4 v;
            v.x = acc[i][jj + 0]; v.y = acc[i][jj + 1];
            v.z = acc[i][jj + 2]; v.w = acc[i][jj + 3];
            if constexpr (EPI >= 1) {
                v.x += bias[gcol + jj + 0]; v.y += bias[gcol + jj + 1];
                v.z += bias[gcol + jj + 2]; v.w += bias[gcol + jj + 3];
            }
            if constexpr (EPI == 2) {
                v.x = tanhf(v.x); v.y = tanhf(v.y);
                v.z = tanhf(v.z); v.w = tanhf(v.w);
            }
            *reinterpret_cast<float4*>(Cp + (size_t)row * ldc + tx * 8 + jj) = v;
        }
    }
}

// ---------------------------------------------------------------------------
// tf32 helpers
// ---------------------------------------------------------------------------
__device__ __forceinline__ unsigned f2tf(float f) {
    unsigned r;
    asm("cvt.rna.tf32.f32 %0, %1;" : "=r"(r) : "f"(f));
    return r;
}
__device__ __forceinline__ void mma_tf32(float* d, const unsigned a[4],
                                         unsigned b0, unsigned b1) {
    asm volatile(
        "mma.sync.aligned.m16n8k8.row.col.f32.tf32.tf32.f32 "
        "{%0,%1,%2,%3},{%4,%5,%6,%7},{%8,%9},{%0,%1,%2,%3};"
        : "+f"(d[0]), "+f"(d[1]), "+f"(d[2]), "+f"(d[3])
        : "r"(a[0]), "r"(a[1]), "r"(a[2]), "r"(a[3]), "r"(b0), "r"(b1));
}

// ---------------------------------------------------------------------------
// LSTM recurrence, tensor-core version.
// Grid: 96 CTAs = 6 streams x 2 batch-halves(64 rows) x 8 gate-groups(32 units).
// Each CTA: its 128 Whh rows resident in smem (tf32) for all 128 steps.
// Per step: G[64x128] = h[64x256] @ W^T via mma.sync tf32; gate math; h -> Y
// (Y doubles as the h-exchange buffer); global barrier over the 8-CTA group;
// reload full h (64x256) from Y.
// ---------------------------------------------------------------------------
__global__ __launch_bounds__(256) void lstm_mma_kernel(
    const float* __restrict__ xpreF, const float* __restrict__ xpreB,
    const float* __restrict__ WhhF, const float* __restrict__ WhhB,
    const float* __restrict__ h_q, const float* __restrict__ c_q,
    const float* __restrict__ h_c, const float* __restrict__ c_c,
    const float* __restrict__ h_c2, const float* __restrict__ c_c2,
    float* __restrict__ Y, int* __restrict__ bars)
{
    extern __shared__ unsigned sm[];
    unsigned* smW = sm;                  // [128][WPAD] tf32 weights
    unsigned* smH = sm + 128 * WPAD;     // [64][HPAD] tf32 h  (aliased by G)
    float*    smG = (float*)smH;         // [64][GPAD] fp32 gates (epilogue phase)

    int bx  = blockIdx.x;
    int sd  = bx >> 4;                   // 0..5  (seq,dir)
    int rem = bx & 15;
    int bg  = rem >> 3;                  // batch half 0/1
    int gg  = rem & 7;                   // gate group 0..7
    int seq = sd >> 1, dir = sd & 1;
    int grp = sd * 2 + bg;               // barrier group 0..11

    int tid  = threadIdx.x;
    int lane = tid & 31, warp = tid >> 5;
    int ly = lane >> 2, lx = lane & 3;
    int mt = warp & 3;                   // m-tile (16 rows)
    int nh = warp >> 2;                  // n-half (64 gate-cols)

    const float* xpre = (dir ? xpreB : xpreF) + (size_t)seq * MBS * G4;
    const float* Whh  = dir ? WhhB : WhhF;
    const float* h0p  = (seq == 0) ? h_q : ((seq == 1) ? h_c : h_c2);
    const float* c0p  = (seq == 0) ? c_q : ((seq == 1) ? c_c : c_c2);

    // ---- load weights into smem (tf32-rounded), rows = g*32+u ----
    for (int i = tid; i < 128 * 256; i += 256) {
        int r = i >> 8, c = i & 255;
        int g = r >> 5, u_ = r & 31;
        smW[r * WPAD + c] = f2tf(Whh[(size_t)(g * 256 + gg * 32 + u_) * 256 + c]);
    }
    // ---- initial h into smem (tf32) ----
    for (int i = tid; i < 64 * 64; i += 256) {
        int r = i >> 6, c4 = (i & 63) * 4;
        float4 v = *(const float4*)&h0p[((size_t)(dir * BB + bg * 64 + r)) * HH + c4];
        uint4 w; w.x = f2tf(v.x); w.y = f2tf(v.y); w.z = f2tf(v.z); w.w = f2tf(v.w);
        *(uint4*)&smH[r * HPAD + c4] = w;
    }
    // ---- c state: thread owns unit u = tid&31, rows m = warp*8 + p ----
    int u  = tid & 31;
    int mb = warp * 8;
    float cst[8];
#pragma unroll
    for (int p = 0; p < 8; p++)
        cst[p] = c0p[((size_t)(dir * BB + bg * 64 + mb + p)) * HH + gg * 32 + u];
    __syncthreads();

    volatile int* vb = (volatile int*)(bars + grp);

    for (int t = 0; t < SQ; t++) {
        int te = dir ? (SQ - 1 - t) : t;

        // ---- MMA phase: acc[nt][0..3] over 8 n-tiles ----
        float acc[8][4];
#pragma unroll
        for (int n = 0; n < 8; n++)
#pragma unroll
            for (int j = 0; j < 4; j++) acc[n][j] = 0.f;

        const unsigned* hA = smH + (mt * 16 + ly) * HPAD + lx;
#pragma unroll 4
        for (int k0 = 0; k0 < 256; k0 += 8) {
            unsigned a[4];
            a[0] = hA[k0];
            a[1] = hA[k0 + 8 * HPAD];
            a[2] = hA[k0 + 4];
            a[3] = hA[k0 + 8 * HPAD + 4];
#pragma unroll
            for (int nt = 0; nt < 8; nt++) {
                const unsigned* wB = smW + (nh * 64 + nt * 8 + ly) * WPAD + k0 + lx;
                mma_tf32(acc[nt], a, wB[0], wB[4]);
            }
        }
        __syncthreads();          // all h reads done before G overwrites the region

        // ---- write G tile to smem ----
#pragma unroll
        for (int nt = 0; nt < 8; nt++) {
            int n0 = nh * 64 + nt * 8 + lx * 2;
            int r0 = mt * 16 + ly;
            *(float2*)&smG[r0 * GPAD + n0]       = make_float2(acc[nt][0], acc[nt][1]);
            *(float2*)&smG[(r0 + 8) * GPAD + n0] = make_float2(acc[nt][2], acc[nt][3]);
        }
        __syncthreads();

        // ---- gate nonlinearity + h out (straight into Y) ----
#pragma unroll
        for (int p = 0; p < 8; p++) {
            int m = mb + p;
            const float* xp = &xpre[(((size_t)(bg * 64 + m)) * SQ + te) * G4 + gg * 32 + u];
            float gi = smG[m * GPAD +      u] + xp[0];
            float gf = smG[m * GPAD + 32 + u] + xp[256];
            float gc = smG[m * GPAD + 64 + u] + xp[512];
            float go = smG[m * GPAD + 96 + u] + xp[768];
            float i_ = 1.f / (1.f + __expf(-gi));
            float f_ = 1.f / (1.f + __expf(-gf));
            float g_ = tanhf(gc);
            float o_ = 1.f / (1.f + __expf(-go));
            float c  = f_ * cst[p] + i_ * g_;
            cst[p] = c;
            float h = o_ * tanhf(c);
            Y[(((size_t)(seq * BB + bg * 64 + m)) * SQ + te) * D2 + dir * HH + gg * 32 + u] = h;
        }

        // ---- release + barrier over the 8 CTAs of this group ----
        __threadfence();
        __syncthreads();
        if (tid == 0) {
            atomicAdd(bars + grp, 1);
            int target = 8 * (t + 1);
            while (*vb < target) { }
            __threadfence();
        }
        __syncthreads();

        // ---- reload full h (all 8 gate-groups' chunks) from Y ----
        for (int i = tid; i < 64 * 64; i += 256) {
            int r = i >> 6, c4 = (i & 63) * 4;
            float4 v = __ldcg((const float4*)&Y[
                (((size_t)(seq * BB + bg * 64 + r)) * SQ + te) * D2 + dir * HH + c4]);
            uint4 w; w.x = f2tf(v.x); w.y = f2tf(v.y); w.z = f2tf(v.z); w.w = f2tf(v.w);
            *(uint4*)&smH[r * HPAD + c4] = w;
        }
        __syncthreads();
    }
}

// ---------------------------------------------------------------------------
// Softmax kernels (unchanged)
// ---------------------------------------------------------------------------
__global__ void row_softmax(const float* __restrict__ Hm, float* __restrict__ AQ)
{
    int warp = (blockIdx.x * blockDim.x + threadIdx.x) >> 5;
    int lane = threadIdx.x & 31;
    const float* base = Hm + (size_t)warp * SQ;
    float v[4], m = -1e30f;
#pragma unroll
    for (int u = 0; u < 4; u++) { v[u] = base[lane + 32 * u]; m = fmaxf(m, v[u]); }
#pragma unroll
    for (int o = 16; o > 0; o >>= 1) m = fmaxf(m, __shfl_xor_sync(0xffffffffu, m, o));
    float s = 0.f;
#pragma unroll
    for (int u = 0; u < 4; u++) { v[u] = __expf(v[u] - m); s += v[u]; }
#pragma unroll
    for (int o = 16; o > 0; o >>= 1) s += __shfl_xor_sync(0xffffffffu, s, o);
    float inv = 1.f / s;
    float* out = AQ + (size_t)warp * SQ;
#pragma unroll
    for (int u = 0; u < 4; u++) out[lane + 32 * u] = v[u] * inv;
}

__global__ void col_softmax(const float* __restrict__ Hm, float* __restrict__ AC)
{
    int warp = (blockIdx.x * blockDim.x + threadIdx.x) >> 5;
    int lane = threadIdx.x & 31;
    int b = warp >> 7, s = warp & 127;
    const float* base = Hm + (size_t)b * SQ * SQ + s;
    float v[4], m = -1e30f;
#pragma unroll
    for (int u = 0; u < 4; u++) { v[u] = base[(size_t)(lane + 32 * u) * SQ]; m = fmaxf(m, v[u]); }
#pragma unroll
    for (int o = 16; o > 0; o >>= 1) m = fmaxf(m, __shfl_xor_sync(0xffffffffu, m, o));
    float sm = 0.f;
#pragma unroll
    for (int u = 0; u < 4; u++) { v[u] = __expf(v[u] - m); sm += v[u]; }
#pragma unroll
    for (int o = 16; o > 0; o >>= 1) sm += __shfl_xor_sync(0xffffffffu, sm, o);
    float inv = 1.f / sm;
    float* out = AC + (size_t)b * SQ * SQ + (size_t)s * SQ;
#pragma unroll
    for (int u = 0; u < 4; u++) out[lane + 32 * u] = v[u] * inv;
}

// ---------------------------------------------------------------------------
// Host-side GEMM dispatch
// ---------------------------------------------------------------------------
static void run_gemm(bool bt, int epi, int M, int N, int K,
                     const float* A, int lda, size_t sA,
                     const float* B, int ldb, size_t sB,
                     float* C, int ldc, size_t sC,
                     const float* bias, int batch)
{
    dim3 grid(N / 128, M / 128, batch), block(256);
    if (bt) {
        if (epi == 0)      sgemm_kernel<true, 0><<<grid, block>>>(M, N, K, A, lda, sA, B, ldb, sB, C, ldc, sC, bias);
        else if (epi == 1) sgemm_kernel<true, 1><<<grid, block>>>(M, N, K, A, lda, sA, B, ldb, sB, C, ldc, sC, bias);
        else               sgemm_kernel<true, 2><<<grid, block>>>(M, N, K, A, lda, sA, B, ldb, sB, C, ldc, sC, bias);
    } else {
        sgemm_kernel<false, 0><<<grid, block>>>(M, N, K, A, lda, sA, B, ldb, sB, C, ldc, sC, bias);
    }
}

// ---------------------------------------------------------------------------
// kernel_launch
// ---------------------------------------------------------------------------
extern "C" void kernel_launch(void* const* d_in, const int* in_sizes, int n_in,
                              void* d_out, int out_size)
{
    (void)in_sizes; (void)n_in; (void)out_size;
    const int*   inQ   = (const int*)d_in[1];
    const int*   inC   = (const int*)d_in[2];
    const int*   inC2  = (const int*)d_in[3];
    const float* hidQ  = (const float*)d_in[4];
    const float* celQ  = (const float*)d_in[5];
    const float* hidC  = (const float*)d_in[6];
    const float* celC  = (const float*)d_in[7];
    const float* hidC2 = (const float*)d_in[8];
    const float* celC2 = (const float*)d_in[9];
    const float* emb   = (const float*)d_in[10];
    const float* WihF  = (const float*)d_in[11];
    const float* WhhF  = (const float*)d_in[12];
    const float* bihF  = (const float*)d_in[13];
    const float* bhhF  = (const float*)d_in[14];
    const float* WihB  = (const float*)d_in[15];
    const float* WhhB  = (const float*)d_in[16];
    const float* bihB  = (const float*)d_in[17];
    const float* bhhB  = (const float*)d_in[18];
    const float* S1W   = (const float*)d_in[19];
    const float* S1b   = (const float*)d_in[20];
    float* out = (float*)d_out;

    void *pX, *pXpF, *pXpB, *pBf, *pBb, *pY, *pCt, *pHm, *pAQ, *pAC, *pBar;
    cudaGetSymbolAddress(&pX,   g_X);
    cudaGetSymbolAddress(&pXpF, g_XpreF);
    cudaGetSymbolAddress(&pXpB, g_XpreB);
    cudaGetSymbolAddress(&pBf,  g_biasf);
    cudaGetSymbolAddress(&pBb,  g_biasb);
    cudaGetSymbolAddress(&pY,   g_Y);
    cudaGetSymbolAddress(&pCt,  g_Ct);
    cudaGetSymbolAddress(&pHm,  g_Hm);
    cudaGetSymbolAddress(&pAQ,  g_AQ);
    cudaGetSymbolAddress(&pAC,  g_AC);
    cudaGetSymbolAddress(&pBar, g_bar);
    float* X    = (float*)pX;
    float* XpF  = (float*)pXpF;
    float* XpB  = (float*)pXpB;
    float* Bf   = (float*)pBf;
    float* Bb   = (float*)pBb;
    float* Y    = (float*)pY;
    float* Ct   = (float*)pCt;
    float* Hm   = (float*)pHm;
    float* AQ   = (float*)pAQ;
    float* AC   = (float*)pAC;
    int*   bars = (int*)pBar;

    cudaFuncSetAttribute(lstm_mma_kernel,
                         cudaFuncAttributeMaxDynamicSharedMemorySize,
                         LSTM_SMEM_BYTES);

    // 1. prep: bias fold + barrier reset
    prep_kernel<<<4, 256>>>(bihF, bhhF, bihB, bhhB, Bf, Bb, bars);

    // 2. embedding gather for all 3 sequences
    embed_kernel<<<12288, 256>>>(inQ, inC, inC2, (const float4*)emb, (float4*)X);

    // 3. input GEMMs (all timesteps at once): Xpre = X @ Wih^T + (bih+bhh)
    run_gemm(true, 1, MX, G4, EE, X, EE, 0, WihF, EE, 0, XpF, G4, 0, Bf, 1);
    run_gemm(true, 1, MX, G4, EE, X, EE, 0, WihB, EE, 0, XpB, G4, 0, Bb, 1);

    // 4. recurrence: tensor-core version, 96 CTAs (all resident)
    lstm_mma_kernel<<<96, 256, LSTM_SMEM_BYTES>>>(
        XpF, XpB, WhhF, WhhB,
        hidQ, celQ, hidC, celC, hidC2, celC2, Y, bars);

    // 5. tanh projections of C and C2 contexts: Ct = tanh(Y_c @ S1_W^T + S1_b)
    run_gemm(true, 2, MBS, D2, D2, Y + (size_t)1 * MBS * D2, D2, 0,
             S1W, D2, 0, Ct, D2, 0, S1b, 1);
    run_gemm(true, 2, MBS, D2, D2, Y + (size_t)2 * MBS * D2, D2, 0,
             S1W, D2, 0, Ct + (size_t)MBS * D2, D2, 0, S1b, 1);

    // 6. attention for pairs (Q,C) and (Q,C2)
    for (int p = 0; p < 2; p++) {
        run_gemm(true, 0, SQ, SQ, D2,
                 Y, D2, (size_t)SQ * D2,
                 Ct + (size_t)p * MBS * D2, D2, (size_t)SQ * D2,
                 Hm, SQ, (size_t)SQ * SQ, nullptr, BB);
        row_softmax<<<2048, 256>>>(Hm, AQ);
        col_softmax<<<2048, 256>>>(Hm, AC);
        float* outMQ = out + (size_t)(2 * p) * OUTREG;
        float* outMC = out + (size_t)(2 * p + 1) * OUTREG;
        run_gemm(false, 0, SQ, D2, SQ,
                 AQ, SQ, (size_t)SQ * SQ,
                 Y, D2, (size_t)SQ * D2,
                 outMQ, D2, (size_t)SQ * D2, nullptr, BB);
        run_gemm(false, 0, SQ, D2, SQ,
                 AC, SQ, (size_t)SQ * SQ,
                 outMQ, D2, (size_t)SQ * D2,
                 outMC, D2, (size_t)SQ * D2, nullptr, BB);
    }
}

// round 4
// speedup vs baseline: 3.1791x; 1.5858x over previous
#include <cuda_runtime.h>
#include <cuda_bf16.h>
#include <math.h>

// ---------------------------------------------------------------------------
// Problem constants
// ---------------------------------------------------------------------------
#define SQ   128            // seq len
#define BB   128            // batch
#define EE   256            // embed dim
#define HH   256            // hidden
#define G4   1024           // 4*H
#define D2   512            // 2*H
#define MBS  (BB*SQ)        // 16384
#define MX   (3*MBS)        // 49152 rows of X
#define OUTREG (BB*SQ*D2)   // 8388608 floats per output tensor

// LSTM-mma geometry
#define WPAD 260
#define HPAD 260
#define GPAD 132
#define LSTM_SMEM_BYTES ((128*WPAD + 64*HPAD) * 4)   // 199,680 B

// ---------------------------------------------------------------------------
// Device scratch
// ---------------------------------------------------------------------------
__device__ float g_X    [3*MBS*EE];     //  50 MB  embedded inputs [seq][b][s][E]
__device__ float g_XpreF[3*MBS*G4];     // 201 MB  X@Wih_f^T + bias_f
__device__ float g_XpreB[3*MBS*G4];     // 201 MB
__device__ float g_biasf[G4];
__device__ float g_biasb[G4];
__device__ float g_Y    [3*MBS*D2];     // 100 MB  BiLSTM outputs [seq][b][s][2H]
__device__ float g_Ct   [2*MBS*D2];     //  67 MB  tanh(S1(C)) for C and C2
__device__ float g_YqT  [MBS*D2];       //  33 MB  per-batch transpose of Q stream
__device__ float g_MQT  [MBS*D2];       //  33 MB  per-batch transpose of MQ
__device__ float g_Hm   [BB*SQ*SQ];     // 8.4 MB
__device__ float g_AQ   [BB*SQ*SQ];
__device__ float g_AC   [BB*SQ*SQ];
__device__ int   g_bar  [12];           // barrier counters (6 streams x 2 halves)

// ---------------------------------------------------------------------------
// tf32 helpers
// ---------------------------------------------------------------------------
__device__ __forceinline__ unsigned f2tf(float f) {
    unsigned r;
    asm("cvt.rna.tf32.f32 %0, %1;" : "=r"(r) : "f"(f));
    return r;
}
__device__ __forceinline__ void mma_tf32(float* d, const unsigned a[4],
                                         unsigned b0, unsigned b1) {
    asm volatile(
        "mma.sync.aligned.m16n8k8.row.col.f32.tf32.tf32.f32 "
        "{%0,%1,%2,%3},{%4,%5,%6,%7},{%8,%9},{%0,%1,%2,%3};"
        : "+f"(d[0]), "+f"(d[1]), "+f"(d[2]), "+f"(d[3])
        : "r"(a[0]), "r"(a[1]), "r"(a[2]), "r"(a[3]), "r"(b0), "r"(b1));
}

// ---------------------------------------------------------------------------
// Prep: bias = bih + bhh ; reset barrier counters
// ---------------------------------------------------------------------------
__global__ void prep_kernel(const float* __restrict__ bihF, const float* __restrict__ bhhF,
                            const float* __restrict__ bihB, const float* __restrict__ bhhB,
                            float* __restrict__ biasf, float* __restrict__ biasb,
                            int* __restrict__ bars)
{
    int gid = blockIdx.x * 256 + threadIdx.x;
    if (gid < G4) {
        biasf[gid] = bihF[gid] + bhhF[gid];
        biasb[gid] = bihB[gid] + bhhB[gid];
    }
    if (gid < 12) bars[gid] = 0;
}

// ---------------------------------------------------------------------------
// Embedding gather: X[seq][b][s][:] = emb[tok[seq][s][b]][:]
// ---------------------------------------------------------------------------
__global__ void embed_kernel(const int* __restrict__ tq, const int* __restrict__ tc,
                             const int* __restrict__ tc2,
                             const float4* __restrict__ emb, float4* __restrict__ X)
{
    int gid = blockIdx.x * 256 + threadIdx.x;      // 3145728 total
    int c4  = gid & 63;
    int row = gid >> 6;                            // 0..49151
    int seq = row / MBS;
    int rb  = row - seq * MBS;
    int b   = rb >> 7, s = rb & 127;
    const int* tok = (seq == 0) ? tq : ((seq == 1) ? tc : tc2);
    int t = tok[s * BB + b];
    X[(size_t)row * 64 + c4] = emb[(size_t)t * 64 + c4];
}

// ---------------------------------------------------------------------------
// tf32 tensor-core GEMM, NT form:  C = A[M,K] * B[N,K]^T  (+bias) (+tanh)
// Tile 128x128, K-chunk 32. 8 warps as 4(m) x 2(n); warp tile 32x64.
// Fragment mappings identical to the (bench-verified) R3 lstm_mma kernel.
// Smem stride 36: conflict-free float4 stores and a/b fragment loads.
// Requires M%128==0, N%128==0, K%32==0.
// ---------------------------------------------------------------------------
template<int EPI>   // 0=none, 1=+bias[n], 2=tanh(x+bias[n])
__global__ __launch_bounds__(256) void tgemm_kernel(
    int M, int N, int K,
    const float* __restrict__ A, int lda, size_t sA,
    const float* __restrict__ B, int ldb, size_t sB,
    float* __restrict__ C, int ldc, size_t sC,
    const float* __restrict__ bias)
{
    __shared__ unsigned As[128 * 36];
    __shared__ unsigned Bs[128 * 36];
    int bx = blockIdx.x, by = blockIdx.y, bz = blockIdx.z;
    const float* Ap = A + (size_t)bz * sA + (size_t)by * 128 * lda;
    const float* Bp = B + (size_t)bz * sB + (size_t)bx * 128 * ldb;
    float* Cp = C + (size_t)bz * sC + (size_t)by * 128 * ldc + (size_t)bx * 128;

    int tid = threadIdx.x, lane = tid & 31, warp = tid >> 5;
    int wm = warp & 3, wn = warp >> 2;
    int ly = lane >> 2, lx = lane & 3;

    float acc[2][8][4];
#pragma unroll
    for (int im = 0; im < 2; im++)
#pragma unroll
        for (int nt = 0; nt < 8; nt++)
#pragma unroll
            for (int j = 0; j < 4; j++) acc[im][nt][j] = 0.f;

    for (int k0 = 0; k0 < K; k0 += 32) {
#pragma unroll
        for (int i = 0; i < 4; i++) {
            int fid = tid + 256 * i;
            int row = fid >> 3, c4 = (fid & 7) * 4;
            float4 av = *reinterpret_cast<const float4*>(Ap + (size_t)row * lda + k0 + c4);
            uint4 aw; aw.x = f2tf(av.x); aw.y = f2tf(av.y); aw.z = f2tf(av.z); aw.w = f2tf(av.w);
            *reinterpret_cast<uint4*>(&As[row * 36 + c4]) = aw;
            float4 bv = *reinterpret_cast<const float4*>(Bp + (size_t)row * ldb + k0 + c4);
            uint4 bw; bw.x = f2tf(bv.x); bw.y = f2tf(bv.y); bw.z = f2tf(bv.z); bw.w = f2tf(bv.w);
            *reinterpret_cast<uint4*>(&Bs[row * 36 + c4]) = bw;
        }
        __syncthreads();
#pragma unroll
        for (int kk = 0; kk < 4; kk++) {
            int k8 = kk * 8;
            unsigned a[2][4];
#pragma unroll
            for (int im = 0; im < 2; im++) {
                int rb = wm * 32 + im * 16;
                a[im][0] = As[(rb + ly) * 36 + k8 + lx];
                a[im][1] = As[(rb + ly + 8) * 36 + k8 + lx];
                a[im][2] = As[(rb + ly) * 36 + k8 + lx + 4];
                a[im][3] = As[(rb + ly + 8) * 36 + k8 + lx + 4];
            }
#pragma unroll
            for (int nt = 0; nt < 8; nt++) {
                int n = wn * 64 + nt * 8 + ly;
                unsigned b0 = Bs[n * 36 + k8 + lx];
                unsigned b1 = Bs[n * 36 + k8 + lx + 4];
                mma_tf32(acc[0][nt], a[0], b0, b1);
                mma_tf32(acc[1][nt], a[1], b0, b1);
            }
        }
        __syncthreads();
    }

#pragma unroll
    for (int im = 0; im < 2; im++) {
#pragma unroll
        for (int nt = 0; nt < 8; nt++) {
            int n0 = wn * 64 + nt * 8 + lx * 2;
            int r0 = wm * 32 + im * 16 + ly;
            float2 v0 = make_float2(acc[im][nt][0], acc[im][nt][1]);
            float2 v1 = make_float2(acc[im][nt][2], acc[im][nt][3]);
            if constexpr (EPI >= 1) {
                float b0v = bias[bx * 128 + n0], b1v = bias[bx * 128 + n0 + 1];
                v0.x += b0v; v0.y += b1v; v1.x += b0v; v1.y += b1v;
            }
            if constexpr (EPI == 2) {
                v0.x = tanhf(v0.x); v0.y = tanhf(v0.y);
                v1.x = tanhf(v1.x); v1.y = tanhf(v1.y);
            }
            *reinterpret_cast<float2*>(&Cp[(size_t)r0 * ldc + n0]) = v0;
            *reinterpret_cast<float2*>(&Cp[(size_t)(r0 + 8) * ldc + n0]) = v1;
        }
    }
}

// ---------------------------------------------------------------------------
// Batched transpose: per batch b, out[d][t] = in[t][d],  in [SQ x D2]
// grid (D2/32, SQ/32, B), block (32,8)
// ---------------------------------------------------------------------------
__global__ void transpose_kernel(const float* __restrict__ in, float* __restrict__ out)
{
    __shared__ float tile[32][33];
    int b = blockIdx.z;
    const float* ip = in + (size_t)b * SQ * D2;
    float* op = out + (size_t)b * SQ * D2;
    int c0 = blockIdx.x * 32, r0 = blockIdx.y * 32;
    int x = threadIdx.x, y = threadIdx.y;
#pragma unroll
    for (int j = 0; j < 32; j += 8)
        tile[y + j][x] = ip[(size_t)(r0 + y + j) * D2 + c0 + x];
    __syncthreads();
#pragma unroll
    for (int j = 0; j < 32; j += 8)
        op[(size_t)(c0 + y + j) * SQ + r0 + x] = tile[x][y + j];
}

// ---------------------------------------------------------------------------
// LSTM recurrence, tensor-core version (unchanged from R3 — verified).
// ---------------------------------------------------------------------------
__global__ __launch_bounds__(256) void lstm_mma_kernel(
    const float* __restrict__ xpreF, const float* __restrict__ xpreB,
    const float* __restrict__ WhhF, const float* __restrict__ WhhB,
    const float* __restrict__ h_q, const float* __restrict__ c_q,
    const float* __restrict__ h_c, const float* __restrict__ c_c,
    const float* __restrict__ h_c2, const float* __restrict__ c_c2,
    float* __restrict__ Y, int* __restrict__ bars)
{
    extern __shared__ unsigned sm[];
    unsigned* smW = sm;                  // [128][WPAD] tf32 weights
    unsigned* smH = sm + 128 * WPAD;     // [64][HPAD] tf32 h  (aliased by G)
    float*    smG = (float*)smH;         // [64][GPAD] fp32 gates

    int bx  = blockIdx.x;
    int sd  = bx >> 4;
    int rem = bx & 15;
    int bg  = rem >> 3;
    int gg  = rem & 7;
    int seq = sd >> 1, dir = sd & 1;
    int grp = sd * 2 + bg;

    int tid  = threadIdx.x;
    int lane = tid & 31, warp = tid >> 5;
    int ly = lane >> 2, lx = lane & 3;
    int mt = warp & 3;
    int nh = warp >> 2;

    const float* xpre = (dir ? xpreB : xpreF) + (size_t)seq * MBS * G4;
    const float* Whh  = dir ? WhhB : WhhF;
    const float* h0p  = (seq == 0) ? h_q : ((seq == 1) ? h_c : h_c2);
    const float* c0p  = (seq == 0) ? c_q : ((seq == 1) ? c_c : c_c2);

    for (int i = tid; i < 128 * 256; i += 256) {
        int r = i >> 8, c = i & 255;
        int g = r >> 5, u_ = r & 31;
        smW[r * WPAD + c] = f2tf(Whh[(size_t)(g * 256 + gg * 32 + u_) * 256 + c]);
    }
    for (int i = tid; i < 64 * 64; i += 256) {
        int r = i >> 6, c4 = (i & 63) * 4;
        float4 v = *(const float4*)&h0p[((size_t)(dir * BB + bg * 64 + r)) * HH + c4];
        uint4 w; w.x = f2tf(v.x); w.y = f2tf(v.y); w.z = f2tf(v.z); w.w = f2tf(v.w);
        *(uint4*)&smH[r * HPAD + c4] = w;
    }
    int u  = tid & 31;
    int mb = warp * 8;
    float cst[8];
#pragma unroll
    for (int p = 0; p < 8; p++)
        cst[p] = c0p[((size_t)(dir * BB + bg * 64 + mb + p)) * HH + gg * 32 + u];
    __syncthreads();

    volatile int* vb = (volatile int*)(bars + grp);

    for (int t = 0; t < SQ; t++) {
        int te = dir ? (SQ - 1 - t) : t;

        float acc[8][4];
#pragma unroll
        for (int n = 0; n < 8; n++)
#pragma unroll
            for (int j = 0; j < 4; j++) acc[n][j] = 0.f;

        const unsigned* hA = smH + (mt * 16 + ly) * HPAD + lx;
#pragma unroll 4
        for (int k0 = 0; k0 < 256; k0 += 8) {
            unsigned a[4];
            a[0] = hA[k0];
            a[1] = hA[k0 + 8 * HPAD];
            a[2] = hA[k0 + 4];
            a[3] = hA[k0 + 8 * HPAD + 4];
#pragma unroll
            for (int nt = 0; nt < 8; nt++) {
                const unsigned* wB = smW + (nh * 64 + nt * 8 + ly) * WPAD + k0 + lx;
                mma_tf32(acc[nt], a, wB[0], wB[4]);
            }
        }
        __syncthreads();

#pragma unroll
        for (int nt = 0; nt < 8; nt++) {
            int n0 = nh * 64 + nt * 8 + lx * 2;
            int r0 = mt * 16 + ly;
            *(float2*)&smG[r0 * GPAD + n0]       = make_float2(acc[nt][0], acc[nt][1]);
            *(float2*)&smG[(r0 + 8) * GPAD + n0] = make_float2(acc[nt][2], acc[nt][3]);
        }
        __syncthreads();

#pragma unroll
        for (int p = 0; p < 8; p++) {
            int m = mb + p;
            const float* xp = &xpre[(((size_t)(bg * 64 + m)) * SQ + te) * G4 + gg * 32 + u];
            float gi = smG[m * GPAD +      u] + xp[0];
            float gf = smG[m * GPAD + 32 + u] + xp[256];
            float gc = smG[m * GPAD + 64 + u] + xp[512];
            float go = smG[m * GPAD + 96 + u] + xp[768];
            float i_ = 1.f / (1.f + __expf(-gi));
            float f_ = 1.f / (1.f + __expf(-gf));
            float g_ = tanhf(gc);
            float o_ = 1.f / (1.f + __expf(-go));
            float c  = f_ * cst[p] + i_ * g_;
            cst[p] = c;
            float h = o_ * tanhf(c);
            Y[(((size_t)(seq * BB + bg * 64 + m)) * SQ + te) * D2 + dir * HH + gg * 32 + u] = h;
        }

        __threadfence();
        __syncthreads();
        if (tid == 0) {
            atomicAdd(bars + grp, 1);
            int target = 8 * (t + 1);
            while (*vb < target) { }
            __threadfence();
        }
        __syncthreads();

        for (int i = tid; i < 64 * 64; i += 256) {
            int r = i >> 6, c4 = (i & 63) * 4;
            float4 v = __ldcg((const float4*)&Y[
                (((size_t)(seq * BB + bg * 64 + r)) * SQ + te) * D2 + dir * HH + c4]);
            uint4 w; w.x = f2tf(v.x); w.y = f2tf(v.y); w.z = f2tf(v.z); w.w = f2tf(v.w);
            *(uint4*)&smH[r * HPAD + c4] = w;
        }
        __syncthreads();
    }
}

// ---------------------------------------------------------------------------
// Softmax kernels (unchanged)
// ---------------------------------------------------------------------------
__global__ void row_softmax(const float* __restrict__ Hm, float* __restrict__ AQ)
{
    int warp = (blockIdx.x * blockDim.x + threadIdx.x) >> 5;
    int lane = threadIdx.x & 31;
    const float* base = Hm + (size_t)warp * SQ;
    float v[4], m = -1e30f;
#pragma unroll
    for (int u = 0; u < 4; u++) { v[u] = base[lane + 32 * u]; m = fmaxf(m, v[u]); }
#pragma unroll
    for (int o = 16; o > 0; o >>= 1) m = fmaxf(m, __shfl_xor_sync(0xffffffffu, m, o));
    float s = 0.f;
#pragma unroll
    for (int u = 0; u < 4; u++) { v[u] = __expf(v[u] - m); s += v[u]; }
#pragma unroll
    for (int o = 16; o > 0; o >>= 1) s += __shfl_xor_sync(0xffffffffu, s, o);
    float inv = 1.f / s;
    float* out = AQ + (size_t)warp * SQ;
#pragma unroll
    for (int u = 0; u < 4; u++) out[lane + 32 * u] = v[u] * inv;
}

__global__ void col_softmax(const float* __restrict__ Hm, float* __restrict__ AC)
{
    int warp = (blockIdx.x * blockDim.x + threadIdx.x) >> 5;
    int lane = threadIdx.x & 31;
    int b = warp >> 7, s = warp & 127;
    const float* base = Hm + (size_t)b * SQ * SQ + s;
    float v[4], m = -1e30f;
#pragma unroll
    for (int u = 0; u < 4; u++) { v[u] = base[(size_t)(lane + 32 * u) * SQ]; m = fmaxf(m, v[u]); }
#pragma unroll
    for (int o = 16; o > 0; o >>= 1) m = fmaxf(m, __shfl_xor_sync(0xffffffffu, m, o));
    float sm = 0.f;
#pragma unroll
    for (int u = 0; u < 4; u++) { v[u] = __expf(v[u] - m); sm += v[u]; }
#pragma unroll
    for (int o = 16; o > 0; o >>= 1) sm += __shfl_xor_sync(0xffffffffu, sm, o);
    float inv = 1.f / sm;
    float* out = AC + (size_t)b * SQ * SQ + (size_t)s * SQ;
#pragma unroll
    for (int u = 0; u < 4; u++) out[lane + 32 * u] = v[u] * inv;
}

// ---------------------------------------------------------------------------
// Host-side GEMM dispatch (tf32 NT)
// ---------------------------------------------------------------------------
static void run_tgemm(int epi, int M, int N, int K,
                      const float* A, int lda, size_t sA,
                      const float* B, int ldb, size_t sB,
                      float* C, int ldc, size_t sC,
                      const float* bias, int batch)
{
    dim3 grid(N / 128, M / 128, batch), block(256);
    if (epi == 0)      tgemm_kernel<0><<<grid, block>>>(M, N, K, A, lda, sA, B, ldb, sB, C, ldc, sC, bias);
    else if (epi == 1) tgemm_kernel<1><<<grid, block>>>(M, N, K, A, lda, sA, B, ldb, sB, C, ldc, sC, bias);
    else               tgemm_kernel<2><<<grid, block>>>(M, N, K, A, lda, sA, B, ldb, sB, C, ldc, sC, bias);
}

// ---------------------------------------------------------------------------
// kernel_launch
// ---------------------------------------------------------------------------
extern "C" void kernel_launch(void* const* d_in, const int* in_sizes, int n_in,
                              void* d_out, int out_size)
{
    (void)in_sizes; (void)n_in; (void)out_size;
    const int*   inQ   = (const int*)d_in[1];
    const int*   inC   = (const int*)d_in[2];
    const int*   inC2  = (const int*)d_in[3];
    const float* hidQ  = (const float*)d_in[4];
    const float* celQ  = (const float*)d_in[5];
    const float* hidC  = (const float*)d_in[6];
    const float* celC  = (const float*)d_in[7];
    const float* hidC2 = (const float*)d_in[8];
    const float* celC2 = (const float*)d_in[9];
    const float* emb   = (const float*)d_in[10];
    const float* WihF  = (const float*)d_in[11];
    const float* WhhF  = (const float*)d_in[12];
    const float* bihF  = (const float*)d_in[13];
    const float* bhhF  = (const float*)d_in[14];
    const float* WihB  = (const float*)d_in[15];
    const float* WhhB  = (const float*)d_in[16];
    const float* bihB  = (const float*)d_in[17];
    const float* bhhB  = (const float*)d_in[18];
    const float* S1W   = (const float*)d_in[19];
    const float* S1b   = (const float*)d_in[20];
    float* out = (float*)d_out;

    void *pX, *pXpF, *pXpB, *pBf, *pBb, *pY, *pCt, *pYqT, *pMQT, *pHm, *pAQ, *pAC, *pBar;
    cudaGetSymbolAddress(&pX,   g_X);
    cudaGetSymbolAddress(&pXpF, g_XpreF);
    cudaGetSymbolAddress(&pXpB, g_XpreB);
    cudaGetSymbolAddress(&pBf,  g_biasf);
    cudaGetSymbolAddress(&pBb,  g_biasb);
    cudaGetSymbolAddress(&pY,   g_Y);
    cudaGetSymbolAddress(&pCt,  g_Ct);
    cudaGetSymbolAddress(&pYqT, g_YqT);
    cudaGetSymbolAddress(&pMQT, g_MQT);
    cudaGetSymbolAddress(&pHm,  g_Hm);
    cudaGetSymbolAddress(&pAQ,  g_AQ);
    cudaGetSymbolAddress(&pAC,  g_AC);
    cudaGetSymbolAddress(&pBar, g_bar);
    float* X    = (float*)pX;
    float* XpF  = (float*)pXpF;
    float* XpB  = (float*)pXpB;
    float* Bf   = (float*)pBf;
    float* Bb   = (float*)pBb;
    float* Y    = (float*)pY;
    float* Ct   = (float*)pCt;
    float* YqT  = (float*)pYqT;
    float* MQT  = (float*)pMQT;
    float* Hm   = (float*)pHm;
    float* AQ   = (float*)pAQ;
    float* AC   = (float*)pAC;
    int*   bars = (int*)pBar;

    cudaFuncSetAttribute(lstm_mma_kernel,
                         cudaFuncAttributeMaxDynamicSharedMemorySize,
                         LSTM_SMEM_BYTES);

    // 1. prep: bias fold + barrier reset
    prep_kernel<<<4, 256>>>(bihF, bhhF, bihB, bhhB, Bf, Bb, bars);

    // 2. embedding gather
    embed_kernel<<<12288, 256>>>(inQ, inC, inC2, (const float4*)emb, (float4*)X);

    // 3. input GEMMs: Xpre = X @ Wih^T + (bih+bhh)   [49152 x 1024 x 256]
    run_tgemm(1, MX, G4, EE, X, EE, 0, WihF, EE, 0, XpF, G4, 0, Bf, 1);
    run_tgemm(1, MX, G4, EE, X, EE, 0, WihB, EE, 0, XpB, G4, 0, Bb, 1);

    // 4. recurrence (tensor-core, 96 resident CTAs)
    lstm_mma_kernel<<<96, 256, LSTM_SMEM_BYTES>>>(
        XpF, XpB, WhhF, WhhB,
        hidQ, celQ, hidC, celC, hidC2, celC2, Y, bars);

    // 5. Ct = tanh(Y_c @ S1_W^T + S1_b)   [16384 x 512 x 512]
    run_tgemm(2, MBS, D2, D2, Y + (size_t)1 * MBS * D2, D2, 0,
              S1W, D2, 0, Ct, D2, 0, S1b, 1);
    run_tgemm(2, MBS, D2, D2, Y + (size_t)2 * MBS * D2, D2, 0,
              S1W, D2, 0, Ct + (size_t)MBS * D2, D2, 0, S1b, 1);

    // 5b. Yq^T (per batch) for the MQ GEMM's B operand
    {
        dim3 tg(D2 / 32, SQ / 32, BB), tb(32, 8);
        transpose_kernel<<<tg, tb>>>(Y, YqT);
    }

    // 6. attention for pairs (Q,C) and (Q,C2)
    for (int p = 0; p < 2; p++) {
        // Hm[b] = Q[b] @ Ct[b]^T   NT: A=Yq [s][d], B=Ct [t][d]
        run_tgemm(0, SQ, SQ, D2,
                  Y, D2, (size_t)SQ * D2,
                  Ct + (size_t)p * MBS * D2, D2, (size_t)SQ * D2,
                  Hm, SQ, (size_t)SQ * SQ, nullptr, BB);
        row_softmax<<<2048, 256>>>(Hm, AQ);
        col_softmax<<<2048, 256>>>(Hm, AC);
        float* outMQ = out + (size_t)(2 * p) * OUTREG;
        float* outMC = out + (size_t)(2 * p + 1) * OUTREG;
        // MQ[b] = AQ[b] @ Q[b]   NT: A=AQ [s][t], B=YqT [d][t]
        run_tgemm(0, SQ, D2, SQ,
                  AQ, SQ, (size_t)SQ * SQ,
                  YqT, SQ, (size_t)SQ * D2,
                  outMQ, D2, (size_t)SQ * D2, nullptr, BB);
        // MQ^T per batch, then MC[b] = AC[b] @ MQ[b]
        {
            dim3 tg(D2 / 32, SQ / 32, BB), tb(32, 8);
            transpose_kernel<<<tg, tb>>>(outMQ, MQT);
        }
        run_tgemm(0, SQ, D2, SQ,
                  AC, SQ, (size_t)SQ * SQ,
                  MQT, SQ, (size_t)SQ * D2,
                  outMC, D2, (size_t)SQ * D2, nullptr, BB);
    }
}